// round 2
// baseline (speedup 1.0000x reference)
#include <cuda_runtime.h>
#include <math.h>
#include <stdint.h>

#define C 16
#define D 512
#define CHUNK_ROWS 256
#define DPB 256           // dims per block in pass 1
#define NPAIRS (C*(C-1)/2)

// ---------------- device scratch (no allocations allowed) ----------------
__device__ float2 g_partial[512 * C * DPB];   // [blk][c][t] (sum, sumsq) = 16 MB
__device__ int    g_counts[C];
__device__ float  g_mean[C * D];
__device__ float  g_within[C * D];
__device__ double g_pairsum[NPAIRS];
__device__ int    g_ids_is64;                 // 1 if batch_ids is int64, else int32

// id accessor safe for either dtype
__device__ __forceinline__ int get_id(const int* ids32, int i, int is64) {
    return is64 ? ids32[2 * i] : ids32[i];    // little-endian low word
}

// ---------------- dtype detection + init ----------------
__global__ void k_detect(const int* __restrict__ ids32, int n) {
    if (threadIdx.x == 0) {
        // int64 values < C have zero high words at odd 32-bit indices.
        // int32 random ids in [0,C) are ~never all-zero across 128 samples.
        int all_zero = 1;
        int lim = n / 2; if (lim > 128) lim = 128;
        for (int i = 0; i < lim; i++) {
            if (ids32[2 * i + 1] != 0) { all_zero = 0; break; }
        }
        g_ids_is64 = all_zero;
    }
    if (threadIdx.x < C) g_counts[threadIdx.x] = 0;
}

// ---------------- class counts ----------------
__global__ void k_counts(const int* __restrict__ ids32, int n) {
    __shared__ int loc[C];
    if (threadIdx.x < C) loc[threadIdx.x] = 0;
    __syncthreads();
    int is64 = g_ids_is64;
    for (int i = blockIdx.x * blockDim.x + threadIdx.x; i < n;
         i += gridDim.x * blockDim.x) {
        int c = get_id(ids32, i, is64) & (C - 1);
        atomicAdd(&loc[c], 1);
    }
    __syncthreads();
    if (threadIdx.x < C) atomicAdd(&g_counts[threadIdx.x], loc[threadIdx.x]);
}

// ---------------- pass 1: per-(class,dim) sum and sumsq, one sweep of hidden ----
// block = (chunk of 256 rows) x (half of the 512 dims). Thread t owns one dim,
// so smem accumulator writes are conflict-free and need no atomics.
__global__ __launch_bounds__(256) void k_pass1(const float* __restrict__ hidden,
                                               const int* __restrict__ ids32) {
    __shared__ float2 acc[C * DPB];           // 32 KB
    __shared__ int cls[CHUNK_ROWS];
    int t = threadIdx.x;
    int half  = blockIdx.x & 1;
    int chunk = blockIdx.x >> 1;
    int rowBase = chunk * CHUNK_ROWS;

    for (int i = t; i < C * DPB; i += blockDim.x) acc[i] = make_float2(0.f, 0.f);
    cls[t] = get_id(ids32, rowBase + t, g_ids_is64) & (C - 1);
    __syncthreads();

    int dim = half * DPB + t;
    const float* p = hidden + (size_t)rowBase * D + dim;
#pragma unroll 4
    for (int r = 0; r < CHUNK_ROWS; r++) {
        int c = cls[r];
        float v = p[(size_t)r * D];
        float2 a = acc[c * DPB + t];
        a.x += v;
        a.y = fmaf(v, v, a.y);
        acc[c * DPB + t] = a;
    }
    __syncthreads();

    float2* out = g_partial + (size_t)blockIdx.x * (C * DPB);
    for (int i = t; i < C * DPB; i += blockDim.x) out[i] = acc[i];
}

// ---------------- pass 2: reduce partials -> mean / within ----------------
__global__ void k_pass2(int nChunks) {
    int g = blockIdx.x * blockDim.x + threadIdx.x;   // 0 .. C*D-1
    if (g >= C * D) return;
    int c  = g >> 9;           // /512
    int dm = g & (D - 1);
    int half = dm >> 8;
    int t    = dm & (DPB - 1);
    double sx = 0.0, sxx = 0.0;
    for (int chunk = 0; chunk < nChunks; chunk++) {
        float2 v = g_partial[(size_t)((chunk << 1) | half) * (C * DPB) + c * DPB + t];
        sx  += (double)v.x;
        sxx += (double)v.y;
    }
    double cnt  = (double)g_counts[c];
    double mean = sx / cnt;
    g_mean[c * D + dm]   = (float)mean;
    g_within[c * D + dm] = (float)(sxx - sx * mean);   // sumsq - n*mean^2
}

// ---------------- fp32 Lentz continued fraction for betainc ----------------
__device__ float betacf_f(float a, float b, float x) {
    const float FPMIN = 1e-30f;
    float qab = a + b, qap = a + 1.f, qam = a - 1.f;
    float cc = 1.f;
    float dd = 1.f - qab * x / qap;
    if (fabsf(dd) < FPMIN) dd = FPMIN;
    dd = 1.f / dd;
    float h = dd;
    for (int m = 1; m <= 250; m++) {
        float fm = (float)m, m2 = 2.f * fm;
        float aa = fm * (b - fm) * x / ((qam + m2) * (a + m2));
        dd = 1.f + aa * dd; if (fabsf(dd) < FPMIN) dd = FPMIN;
        cc = 1.f + aa / cc; if (fabsf(cc) < FPMIN) cc = FPMIN;
        dd = 1.f / dd;
        h *= dd * cc;
        aa = -(a + fm) * (qab + fm) * x / ((a + m2) * (qap + m2));
        dd = 1.f + aa * dd; if (fabsf(dd) < FPMIN) dd = FPMIN;
        cc = 1.f + aa / cc; if (fabsf(cc) < FPMIN) cc = FPMIN;
        dd = 1.f / dd;
        float del = dd * cc;
        h *= del;
        if (fabsf(del - 1.f) < 1e-7f) break;
    }
    return h;
}

// ---------------- pair kernel: x -> sort -> betainc(top-K) -> sum log ------
__global__ __launch_bounds__(D) void k_pairs(const int* __restrict__ dptr) {
    __shared__ float sx[D];
    __shared__ float sred[D];
    __shared__ float s_lnB;
    int t = threadIdx.x;

    // decode pair (i,j), i<j
    int bid = blockIdx.x;
    int i = 0, rem = bid;
    while (rem >= C - 1 - i) { rem -= C - 1 - i; i++; }
    int j = i + 1 + rem;

    float ni = (float)g_counts[i], nj = (float)g_counts[j];
    float pc = ni + nj;
    float d2 = pc - 2.f;
    if (d2 == 0.f) d2 = 1e-5f;
    float b = d2 * 0.5f;

    if (t == 0) {
        // fp64 once per pair: avoids fp32 lgamma cancellation at b ~ 4095
        double bd = (double)b;
        s_lnB = (float)(lgamma(0.5) + lgamma(bd) - lgamma(0.5 + bd));
    }

    float mi = g_mean[i * D + t],  mj = g_mean[j * D + t];
    float wi = g_within[i * D + t], wj = g_within[j * D + t];
    float hd   = (mi - mj) * 0.5f;
    float betw = hd * hd * pc;
    float x = betw / (betw + wi + wj);
    x = fminf(fmaxf(x, 1e-37f), 1.f - 1e-5f);
    sx[t] = x;
    __syncthreads();

    // bitonic sort descending; betainc monotone in x => top-k(betainc)=betainc(top-k(x))
    for (int k = 2; k <= D; k <<= 1) {
        for (int jj = k >> 1; jj > 0; jj >>= 1) {
            int ixj = t ^ jj;
            if (ixj > t) {
                float a0 = sx[t], b0 = sx[ixj];
                bool desc = ((t & k) == 0);
                if (desc ? (a0 < b0) : (a0 > b0)) { sx[t] = b0; sx[ixj] = a0; }
            }
            __syncthreads();
        }
    }

    int K = 64;
    if (dptr) {
        int kv = dptr[0];
        if (kv >= 1 && kv <= D) K = kv;
    }

    const float a = 0.5f;
    float val = 0.f;
    if (t < K) {
        float xv  = sx[t];
        float lnB = s_lnB;
        float lbt = a * logf(xv) + b * log1pf(-xv) - lnB;
        float thresh = (a + 1.f) / (a + b + 2.f);
        float logI;
        if (xv < thresh) {
            float cf = betacf_f(a, b, xv);
            if (cf < 1e-30f) cf = 1e-30f;
            logI = lbt + logf(cf) - logf(a);
        } else {
            float cf   = betacf_f(b, a, 1.f - xv);
            float tail = expf(lbt) * cf / b;
            if (tail > 0.99999994f) tail = 0.99999994f;
            logI = log1pf(-tail);
        }
        val = logI;
    }
    sred[t] = val;
    __syncthreads();
    for (int s = D / 2; s > 0; s >>= 1) {
        if (t < s) sred[t] += sred[t + s];
        __syncthreads();
    }
    if (t == 0) g_pairsum[bid] = (double)sred[0];
}

// ---------------- final deterministic scalar reduce ----------------
__global__ void k_final(float* out) {
    if (threadIdx.x == 0) {
        double tot = 0.0;
        for (int p = 0; p < NPAIRS; p++) tot += g_pairsum[p];
        out[0] = (float)(-tot);
    }
}

// ---------------- launch ----------------
extern "C" void kernel_launch(void* const* d_in, const int* in_sizes, int n_in,
                              void* d_out, int out_size) {
    const float* hidden = (const float*)d_in[0];
    const int*   ids32  = (const int*)d_in[1];
    const int*   dptr   = (n_in > 2) ? (const int*)d_in[2] : nullptr;

    int N = in_sizes[0] / D;            // 65536
    int nChunks = N / CHUNK_ROWS;       // 256

    k_detect<<<1, 32>>>(ids32, N);
    k_counts<<<64, 256>>>(ids32, N);
    k_pass1 <<<nChunks * 2, 256>>>(hidden, ids32);
    k_pass2 <<<(C * D + 255) / 256, 256>>>(nChunks);
    k_pairs <<<NPAIRS, D>>>(dptr);
    k_final <<<1, 32>>>((float*)d_out);
}